// round 15
// baseline (speedup 1.0000x reference)
#include <cuda_runtime.h>
#include <cuda_bf16.h>

// FilterEnhance via Gram reformulation: loss*8388608 = Q - 2C + S.
// Q = <M,G>, M = W^T W; G(c,t,c',t') = r[c,c',d] - H[cc,d][max(a,0)] - T[cc,d][max(-a,0)],
// a = t-127, d = t'-t. r = batch lag-correlations; H/T = edge prefix sums.
// C = sum_f W[f,c',tau] * r[f%8, c', tau-127]; S = 128 * sum_c r[c,c,0].
// Round 15: k_ht2 with 4 persistent partial accumulators per output (breaks the
// 16-deep FFMA dependency chain, ~4x shorter critical path); k_zero_r folded
// into k_prep.

typedef unsigned int u32;
typedef unsigned long long u64;

__device__ double g_acc;                  // static 0; k_final resets
__device__ float g_r[8 * 512 * 8];        // [c'][di][c], di = d+255
__device__ float g_H[64 * 128 * 512];     // [cc][m][di]
__device__ float g_T[64 * 128 * 512];
__device__ float g_M[2048 * 2048];
__device__ uint4 g_Wt4[16 * 16 * 1024];   // tiles [kt*16+q]: 128 k-rows x 64 F bf16, swizzled

__device__ __forceinline__ u32 smem_u32(const void* p) {
    u32 a; asm("{ .reg .u64 t; cvta.to.shared.u64 t, %1; cvt.u32.u64 %0, t; }" : "=r"(a) : "l"(p)); return a;
}
__device__ __forceinline__ u64 to_global(const void* p) {
    u64 g; asm("cvta.to.global.u64 %0, %1;" : "=l"(g) : "l"(p)); return g;
}
__device__ __forceinline__ void cpa16(u32 dst, u64 gsrc) {
    asm volatile("cp.async.cg.shared.global [%0], [%1], 16;" :: "r"(dst), "l"(gsrc) : "memory");
}
#define CP_COMMIT() asm volatile("cp.async.commit_group;" ::: "memory")
#define CP_WAIT0()  asm volatile("cp.async.wait_group 0;" ::: "memory")
__device__ __forceinline__ u32 lds32(u32 a) {
    u32 v; asm volatile("ld.shared.b32 %0,[%1];" : "=r"(v) : "r"(a)); return v;
}
__device__ __forceinline__ void ldmatrix_x4(u32& a0, u32& a1, u32& a2, u32& a3, u32 addr) {
    asm volatile("ldmatrix.sync.aligned.m8n8.x4.shared.b16 {%0,%1,%2,%3}, [%4];"
                 : "=r"(a0), "=r"(a1), "=r"(a2), "=r"(a3) : "r"(addr));
}
__device__ __forceinline__ void mma16816(float& d0, float& d1, float& d2, float& d3,
                                         u32 a0, u32 a1, u32 a2, u32 a3, u32 b0, u32 b1) {
    asm volatile("mma.sync.aligned.m16n8k16.row.col.f32.bf16.bf16.f32 "
                 "{%0,%1,%2,%3}, {%4,%5,%6,%7}, {%8,%9}, {%0,%1,%2,%3};"
                 : "+f"(d0), "+f"(d1), "+f"(d2), "+f"(d3)
                 : "r"(a0), "r"(a1), "r"(a2), "r"(a3), "r"(b0), "r"(b1));
}
__device__ __forceinline__ u32 bfb(float x) {
    return (u32)__bfloat16_as_ushort(__float2bfloat16(x));
}

// Wt[k][F] bf16, swizzled tiles. k = c*255+tau (2040, pad 2048), F = f (1024).
// Also zeroes g_r (first 128 blocks).
__global__ void k_prep(const float* __restrict__ F) {
    if (blockIdx.x < 128) g_r[blockIdx.x * 256 + threadIdx.x] = 0.0f;
    __nv_bfloat16* W = (__nv_bfloat16*)g_Wt4;
    const int total = 16 * 16 * 8192;
    for (int e = blockIdx.x * blockDim.x + threadIdx.x; e < total; e += gridDim.x * blockDim.x) {
        int tile = e >> 13, off = e & 8191;
        int kt = tile >> 4, q = tile & 15;
        int kl = off >> 6, fl = off & 63;
        int k = kt * 128 + kl, Fi = q * 64 + fl;
        float v = (k < 2040) ? F[(size_t)Fi * 2040 + k] : 0.0f;
        u32 sb2 = (u32)(kl * 128 + fl * 2);
        sb2 ^= (sb2 >> 3) & 0x70;
        W[(size_t)tile * 8192 + (sb2 >> 1)] = __float2bfloat16(v);
    }
}

// r[c', di, c] += sum_u bf16(Xp[c',u+di-255]) * bf16(X[c,u]) over one batch b.
// GEMM: M = 512 lags split over 2 blocks; N = 8 channels; K = 8192.
#define CORR_SMEM ((4360 * 2 + 4096) * 4)
__global__ __launch_bounds__(256, 1) void k_corr(const float* __restrict__ X) {
    extern __shared__ u32 cs[];
    u32* xpE = cs; u32* xpO = cs + 4360; u32* xb = cs + 8720;
    const int tid = threadIdx.x, wid = tid >> 5, lane = tid & 31;
    const int dh = blockIdx.x, cp = blockIdx.y, b = blockIdx.z;
    const float* Xb = X + (size_t)b * 65536;
    const float* Xc = Xb + cp * 8192;

    for (int i = tid; i < 4360; i += 256) {     // arr[j] = Xp[c', j-255], pairs
        int t = 2 * i - 255;
        float x0 = (t >= 0 && t < 8192) ? Xc[t] : 0.0f;
        float x1 = (t + 1 >= 0 && t + 1 < 8192) ? Xc[t + 1] : 0.0f;
        float x2 = (t + 2 >= 0 && t + 2 < 8192) ? Xc[t + 2] : 0.0f;
        xpE[i] = (bfb(x1) << 16) | bfb(x0);
        xpO[i] = (bfb(x2) << 16) | bfb(x1);
    }

    float acc[2][4];
    #pragma unroll
    for (int mt = 0; mt < 2; mt++) { acc[mt][0] = acc[mt][1] = acc[mt][2] = acc[mt][3] = 0.0f; }

    const int r0 = lane >> 2, kp = (lane & 3) * 2;
    const int d0 = dh * 256 + wid * 32;
    const u32* arr = (r0 & 1) ? xpO : xpE;
    const int Ioff = (d0 + r0 + kp) >> 1;
    const int nb = (lane >> 2) * 512 + (lane & 3);

    for (int mc = 0; mc < 8; mc++) {
        __syncthreads();
        for (int i2 = tid; i2 < 4096; i2 += 256) {
            int ch = i2 >> 9, ii = i2 & 511;
            float2 v = *(const float2*)(Xb + ch * 8192 + mc * 1024 + 2 * ii);
            xb[i2] = (bfb(v.y) << 16) | bfb(v.x);
        }
        __syncthreads();
        const int Ib = mc * 512 + Ioff;
        #pragma unroll 8
        for (int kc = 0; kc < 64; kc++) {
            int I = Ib + kc * 8;
            u32 qa[5];
            #pragma unroll
            for (int j = 0; j < 5; j++) qa[j] = arr[I + 4 * j];
            u32 b0 = xb[nb + kc * 8], b1 = xb[nb + kc * 8 + 4];
            #pragma unroll
            for (int mt = 0; mt < 2; mt++)
                mma16816(acc[mt][0], acc[mt][1], acc[mt][2], acc[mt][3],
                         qa[2 * mt], qa[2 * mt + 1], qa[2 * mt + 1], qa[2 * mt + 2], b0, b1);
        }
    }
    const int c0 = (lane & 3) * 2;
    #pragma unroll
    for (int mt = 0; mt < 2; mt++) {
        int di = d0 + mt * 16 + r0;
        atomicAdd(&g_r[(cp * 512 + di) * 8 + c0],     acc[mt][0]);
        atomicAdd(&g_r[(cp * 512 + di) * 8 + c0 + 1], acc[mt][1]);
        atomicAdd(&g_r[(cp * 512 + di + 8) * 8 + c0],     acc[mt][2]);
        atomicAdd(&g_r[(cp * 512 + di + 8) * 8 + c0 + 1], acc[mt][3]);
    }
}

// Fused edge products + prefix scan, register-windowed, partial accumulators.
// Head (tail=0): product at step m for output di: xc[m]*xp[m+di].
// Tail (tail=1): product: xc[m]*xp[126-m+di].
// Thread t handles di = 2t, 2t+1 with a sliding float2 window per b.
// Prefix kept as 4 persistent partials (4 batches each) -> FFMA chain depth 4.
#define HT_SMEM ((16 * 640 + 128 * 16) * 4)
__global__ __launch_bounds__(256) void k_ht2(const float* __restrict__ X) {
    extern __shared__ float hs[];
    float* xp = hs;                 // [b][640]
    float* xc = hs + 16 * 640;      // [m][16]  (m = 0..127, row 127 zero)
    const int cc = blockIdx.x, c = cc >> 3, cq = cc & 7;
    const int tail = blockIdx.y;
    const int t = threadIdx.x;      // di = 2t, 2t+1
    float* O = (tail ? g_T : g_H) + (size_t)(cc * 128) * 512;

    for (int i = t; i < 16 * 640; i += 256) {
        int b = i / 640, j = i - b * 640;
        const float* Xq = X + (size_t)b * 65536 + cq * 8192;
        float v;
        if (!tail) v = (j >= 255 && j < 637) ? Xq[j - 255] : 0.0f;
        else       v = (j <= 381) ? Xq[7810 + j] : 0.0f;
        xp[i] = v;
    }
    for (int i = t; i < 128 * 16; i += 256) {
        int m = i >> 4, b = i & 15;
        const float* Xc2 = X + (size_t)b * 65536 + c * 8192;
        xc[i] = (m < 127) ? (tail ? Xc2[8191 - m] : Xc2[m]) : 0.0f;
    }
    __syncthreads();

    const float2* xp2 = (const float2*)xp;   // [b][320] pairs
    float2 Pc[16], Pn[16];
    #pragma unroll
    for (int b = 0; b < 16; b++)
        Pc[b] = xp2[b * 320 + (tail ? (63 + t) : t)];

    float p0[4], p1[4];                       // persistent partials (4 b each)
    #pragma unroll
    for (int g = 0; g < 4; g++) { p0[g] = 0.0f; p1[g] = 0.0f; }
    *(float2*)&O[2 * t] = make_float2(0.0f, 0.0f);   // m = 0 row

    for (int s = 0; s < 64; s++) {
        int pi = tail ? (62 - s + t) : (t + s + 1);
        if (pi < 0) pi = 0;                          // tail s=63,t=0 guard (unused value)
        #pragma unroll
        for (int b = 0; b < 16; b++)
            Pn[b] = xp2[b * 320 + pi];

        // step m = 2s
        {
            const float4* xr = (const float4*)&xc[(2 * s) * 16];
            float4 x0 = xr[0], x1 = xr[1], x2 = xr[2], x3 = xr[3];
            float xv[16] = {x0.x, x0.y, x0.z, x0.w, x1.x, x1.y, x1.z, x1.w,
                            x2.x, x2.y, x2.z, x2.w, x3.x, x3.y, x3.z, x3.w};
            #pragma unroll
            for (int g = 0; g < 4; g++)
                #pragma unroll
                for (int q = 0; q < 4; q++) {
                    int b = g * 4 + q;
                    p0[g] += xv[b] * Pc[b].x;
                    p1[g] += xv[b] * Pc[b].y;
                }
            *(float2*)&O[(size_t)(2 * s + 1) * 512 + 2 * t] =
                make_float2((p0[0] + p0[1]) + (p0[2] + p0[3]),
                            (p1[0] + p1[1]) + (p1[2] + p1[3]));
        }
        // step m = 2s+1 (exists for s < 63: m <= 126)
        if (s < 63) {
            const float4* xr = (const float4*)&xc[(2 * s + 1) * 16];
            float4 x0 = xr[0], x1 = xr[1], x2 = xr[2], x3 = xr[3];
            float xv[16] = {x0.x, x0.y, x0.z, x0.w, x1.x, x1.y, x1.z, x1.w,
                            x2.x, x2.y, x2.z, x2.w, x3.x, x3.y, x3.z, x3.w};
            if (!tail) {
                #pragma unroll
                for (int g = 0; g < 4; g++)
                    #pragma unroll
                    for (int q = 0; q < 4; q++) {
                        int b = g * 4 + q;
                        p0[g] += xv[b] * Pc[b].y;
                        p1[g] += xv[b] * Pn[b].x;
                    }
            } else {
                #pragma unroll
                for (int g = 0; g < 4; g++)
                    #pragma unroll
                    for (int q = 0; q < 4; q++) {
                        int b = g * 4 + q;
                        p0[g] += xv[b] * Pn[b].y;
                        p1[g] += xv[b] * Pc[b].x;
                    }
            }
            *(float2*)&O[(size_t)(2 * s + 2) * 512 + 2 * t] =
                make_float2((p0[0] + p0[1]) + (p0[2] + p0[3]),
                            (p1[0] + p1[1]) + (p1[2] + p1[3]));
        }
        #pragma unroll
        for (int b = 0; b < 16; b++) Pc[b] = Pn[b];
    }
}

// M = Wt * Wt^T over F: CTA 128x128, K = 1024 in 16 chunks of 64.
#define GEMM_SMEM (65536 + 1024)
__global__ __launch_bounds__(256, 2) void k_gemm() {
    extern __shared__ char sm[];
    u32 raw = smem_u32(sm);
    u32 sb = (raw + 1023u) & ~1023u;
    const int tid = threadIdx.x, wid = tid >> 5, lane = tid & 31;
    const int warp_m = wid & 1, warp_n = wid >> 1;
    const int bx = blockIdx.x, by = blockIdx.y;
    const u64 wt = to_global(g_Wt4);

    {   // prologue chunk 0
        u64 sa = wt + (u64)(by * 16) * 16384u;
        u64 sg = wt + (u64)(bx * 16) * 16384u;
        for (int i = 0; i < 4; i++) { int e = tid + i * 256; cpa16(sb + e * 16u, sa + (u64)e * 16u); }
        for (int i = 0; i < 4; i++) { int e = tid + i * 256; cpa16(sb + 16384u + e * 16u, sg + (u64)e * 16u); }
        CP_COMMIT();
    }

    float acc[4][4][4];
    #pragma unroll
    for (int mt = 0; mt < 4; mt++)
        #pragma unroll
        for (int nt = 0; nt < 4; nt++)
            #pragma unroll
            for (int r = 0; r < 4; r++) acc[mt][nt][r] = 0.0f;

    const u32 sw = (u32)((lane & 7) << 4);
    const u32 lanecol = (u32)((lane >> 4) * 16);
    u32 am[4], bn[4], bsw[4];
    #pragma unroll
    for (int mt = 0; mt < 4; mt++)
        am[mt] = (u32)(warp_m * 64 + (lane & 15) + mt * 16) * 128u + (lanecol ^ sw);
    #pragma unroll
    for (int nt = 0; nt < 4; nt++) {
        u32 n = (u32)(warp_n * 32 + nt * 8 + (lane >> 2));
        bn[nt] = n * 128u + (u32)((lane & 3) * 4);
        bsw[nt] = (n & 7) << 4;
    }

    for (int ci = 0; ci < 16; ci++) {
        CP_WAIT0();
        __syncthreads();
        if (ci < 15) {
            u32 p = (u32)((ci + 1) & 1) * 32768u;
            u64 sa = wt + (u64)(by * 16 + ci + 1) * 16384u;
            u64 sg = wt + (u64)(bx * 16 + ci + 1) * 16384u;
            for (int i = 0; i < 4; i++) { int e = tid + i * 256; cpa16(sb + p + e * 16u, sa + (u64)e * 16u); }
            for (int i = 0; i < 4; i++) { int e = tid + i * 256; cpa16(sb + p + 16384u + e * 16u, sg + (u64)e * 16u); }
            CP_COMMIT();
        }
        const u32 at = sb + (u32)(ci & 1) * 32768u;
        const u32 bt = at + 16384u;
        #pragma unroll
        for (int ks = 0; ks < 4; ks++) {
            u32 bf0[4], bf1[4];
            #pragma unroll
            for (int nt = 0; nt < 4; nt++) {
                u32 x = bn[nt] + (u32)(ks * 32);
                bf0[nt] = lds32(bt + (x ^ bsw[nt]));
                bf1[nt] = lds32(bt + ((x + 16u) ^ bsw[nt]));
            }
            #pragma unroll
            for (int mt = 0; mt < 4; mt++) {
                u32 a0, a1, a2, a3;
                ldmatrix_x4(a0, a1, a2, a3, (at + am[mt]) ^ (u32)(ks << 5));
                #pragma unroll
                for (int nt = 0; nt < 4; nt++)
                    mma16816(acc[mt][nt][0], acc[mt][nt][1], acc[mt][nt][2], acc[mt][nt][3],
                             a0, a1, a2, a3, bf0[nt], bf1[nt]);
            }
        }
    }
    #pragma unroll
    for (int mt = 0; mt < 4; mt++) {
        int kR = by * 128 + warp_m * 64 + mt * 16 + (lane >> 2);
        #pragma unroll
        for (int nt = 0; nt < 4; nt++) {
            int col = bx * 128 + warp_n * 32 + nt * 8 + (lane & 3) * 2;
            *(float2*)&g_M[(size_t)kR * 2048 + col] = make_float2(acc[mt][nt][0], acc[mt][nt][1]);
            *(float2*)&g_M[(size_t)(kR + 8) * 2048 + col] = make_float2(acc[mt][nt][2], acc[mt][nt][3]);
        }
    }
}

__global__ __launch_bounds__(256, 4) void k_qdot() {
    __shared__ unsigned char lc[2040];
    __shared__ unsigned short lt[2040];
    __shared__ float ws[8];
    const int tid = threadIdx.x;
    for (int i = tid; i < 2040; i += 256) { int q = i / 255; lc[i] = (unsigned char)q; lt[i] = (unsigned short)(i - q * 255); }
    __syncthreads();
    const int k = blockIdx.x;
    const int kc = k / 255, kt = k - kc * 255;
    const int mh = kt > 127 ? kt - 127 : 0;
    const int ml = kt < 127 ? 127 - kt : 0;
    const float* Mrow = g_M + (size_t)k * 2048;
    const size_t Hb = (size_t)(kc * 1024 + mh) * 512;
    const size_t Tb = (size_t)(kc * 1024 + ml) * 512;
    float a = 0.0f;
    for (int k2 = tid; k2 < 2040; k2 += 256) {
        int cp = lc[k2];
        int di = (int)lt[k2] - kt + 255;
        float G = g_r[((cp << 9) + di) * 8 + kc]
                - g_H[Hb + (size_t)cp * 65536 + di]
                - g_T[Tb + (size_t)cp * 65536 + di];
        a += Mrow[k2] * G;
    }
    #pragma unroll
    for (int o = 16; o; o >>= 1) a += __shfl_xor_sync(0xffffffffu, a, o);
    if ((tid & 31) == 0) ws[tid >> 5] = a;
    __syncthreads();
    if (tid == 0) {
        float s = 0.0f;
        for (int w = 0; w < 8; w++) s += ws[w];
        atomicAdd(&g_acc, (double)s);
    }
}

__global__ __launch_bounds__(256, 4) void k_cross(const float* __restrict__ F) {
    __shared__ float ws[8];
    const int f = blockIdx.x, cf = f & 7;
    const float* Wf = F + (size_t)f * 2040;
    float a = 0.0f;
    for (int k = threadIdx.x; k < 2040; k += 256) {
        int cp = k / 255, tau = k - cp * 255;
        a += Wf[k] * g_r[((cp << 9) + tau + 128) * 8 + cf];
    }
    #pragma unroll
    for (int o = 16; o; o >>= 1) a += __shfl_xor_sync(0xffffffffu, a, o);
    if ((threadIdx.x & 31) == 0) ws[threadIdx.x >> 5] = a;
    __syncthreads();
    if (threadIdx.x == 0) {
        float s = 0.0f;
        for (int w = 0; w < 8; w++) s += ws[w];
        atomicAdd(&g_acc, -2.0 * (double)s);
    }
}

__global__ void k_final(float* out) {
    double s = g_acc;
    for (int c = 0; c < 8; c++) s += 128.0 * (double)g_r[((c << 9) + 255) * 8 + c];
    out[0] = (float)(s * (1.0 / 8388608.0));
    g_acc = 0.0;
}

extern "C" void kernel_launch(void* const* d_in, const int* in_sizes, int n_in,
                              void* d_out, int out_size) {
    const float* X = (const float*)d_in[0];
    const float* F = (const float*)d_in[1];
    if (n_in >= 2 && in_sizes[0] == 16 * 64 * 8 * 255) {
        const float* t = X; X = F; F = t;
    }
    static int configured = 0;
    if (!configured) {
        cudaFuncSetAttribute(k_corr, cudaFuncAttributeMaxDynamicSharedMemorySize, CORR_SMEM);
        cudaFuncSetAttribute(k_ht2, cudaFuncAttributeMaxDynamicSharedMemorySize, HT_SMEM);
        cudaFuncSetAttribute(k_gemm, cudaFuncAttributeMaxDynamicSharedMemorySize, GEMM_SMEM);
        configured = 1;
    }
    k_prep<<<2048, 256>>>(F);                      // also zeroes g_r
    k_corr<<<dim3(2, 8, 16), 256, CORR_SMEM>>>(X);
    k_ht2<<<dim3(64, 2), 256, HT_SMEM>>>(X);
    k_gemm<<<dim3(16, 16), 256, GEMM_SMEM>>>();
    k_qdot<<<2040, 256>>>();
    k_cross<<<1024, 256>>>(F);
    k_final<<<1, 1>>>((float*)d_out);
}

// round 17
// speedup vs baseline: 1.1109x; 1.1109x over previous
#include <cuda_runtime.h>
#include <cuda_bf16.h>

// FilterEnhance via Gram reformulation: loss*8388608 = Q - 2C + S.
// Q = <M,G>, M = W^T W; G(c,t,c',t') = r[c,c',d] - H[cc,d][max(a,0)] - T[cc,d][max(-a,0)],
// a = t-127, d = t'-t. r = batch lag-correlations; H/T = edge prefix sums.
// C = sum_f W[f,c',tau] * r[f%8, c', tau-127]; S = 128 * sum_c r[c,c,0].
// Round 17 = Round 16 resubmit (infra flake): symmetric-M/G halvings --
// k_gemm upper-triangle tiles only (136 CTAs); k_qdot j >= k with weight 2
// off-diagonal, balanced row-pairing (1020 blocks).

typedef unsigned int u32;
typedef unsigned long long u64;

__device__ double g_acc;                  // static 0; k_final resets
__device__ float g_r[8 * 512 * 8];        // [c'][di][c], di = d+255
__device__ float g_H[64 * 128 * 512];     // [cc][m][di]
__device__ float g_T[64 * 128 * 512];
__device__ float g_M[2048 * 2048];
__device__ uint4 g_Wt4[16 * 16 * 1024];   // tiles [kt*16+q]: 128 k-rows x 64 F bf16, swizzled

__device__ __forceinline__ u32 smem_u32(const void* p) {
    u32 a; asm("{ .reg .u64 t; cvta.to.shared.u64 t, %1; cvt.u32.u64 %0, t; }" : "=r"(a) : "l"(p)); return a;
}
__device__ __forceinline__ u64 to_global(const void* p) {
    u64 g; asm("cvta.to.global.u64 %0, %1;" : "=l"(g) : "l"(p)); return g;
}
__device__ __forceinline__ void cpa16(u32 dst, u64 gsrc) {
    asm volatile("cp.async.cg.shared.global [%0], [%1], 16;" :: "r"(dst), "l"(gsrc) : "memory");
}
#define CP_COMMIT() asm volatile("cp.async.commit_group;" ::: "memory")
#define CP_WAIT0()  asm volatile("cp.async.wait_group 0;" ::: "memory")
__device__ __forceinline__ u32 lds32(u32 a) {
    u32 v; asm volatile("ld.shared.b32 %0,[%1];" : "=r"(v) : "r"(a)); return v;
}
__device__ __forceinline__ void ldmatrix_x4(u32& a0, u32& a1, u32& a2, u32& a3, u32 addr) {
    asm volatile("ldmatrix.sync.aligned.m8n8.x4.shared.b16 {%0,%1,%2,%3}, [%4];"
                 : "=r"(a0), "=r"(a1), "=r"(a2), "=r"(a3) : "r"(addr));
}
__device__ __forceinline__ void mma16816(float& d0, float& d1, float& d2, float& d3,
                                         u32 a0, u32 a1, u32 a2, u32 a3, u32 b0, u32 b1) {
    asm volatile("mma.sync.aligned.m16n8k16.row.col.f32.bf16.bf16.f32 "
                 "{%0,%1,%2,%3}, {%4,%5,%6,%7}, {%8,%9}, {%0,%1,%2,%3};"
                 : "+f"(d0), "+f"(d1), "+f"(d2), "+f"(d3)
                 : "r"(a0), "r"(a1), "r"(a2), "r"(a3), "r"(b0), "r"(b1));
}
__device__ __forceinline__ u32 bfb(float x) {
    return (u32)__bfloat16_as_ushort(__float2bfloat16(x));
}

// Wt[k][F] bf16, swizzled tiles. k = c*255+tau (2040, pad 2048), F = f (1024).
// Also zeroes g_r (first 128 blocks).
__global__ void k_prep(const float* __restrict__ F) {
    if (blockIdx.x < 128) g_r[blockIdx.x * 256 + threadIdx.x] = 0.0f;
    __nv_bfloat16* W = (__nv_bfloat16*)g_Wt4;
    const int total = 16 * 16 * 8192;
    for (int e = blockIdx.x * blockDim.x + threadIdx.x; e < total; e += gridDim.x * blockDim.x) {
        int tile = e >> 13, off = e & 8191;
        int kt = tile >> 4, q = tile & 15;
        int kl = off >> 6, fl = off & 63;
        int k = kt * 128 + kl, Fi = q * 64 + fl;
        float v = (k < 2040) ? F[(size_t)Fi * 2040 + k] : 0.0f;
        u32 sb2 = (u32)(kl * 128 + fl * 2);
        sb2 ^= (sb2 >> 3) & 0x70;
        W[(size_t)tile * 8192 + (sb2 >> 1)] = __float2bfloat16(v);
    }
}

// r[c', di, c] += sum_u bf16(Xp[c',u+di-255]) * bf16(X[c,u]) over one batch b.
// GEMM: M = 512 lags split over 2 blocks; N = 8 channels; K = 8192.
#define CORR_SMEM ((4360 * 2 + 4096) * 4)
__global__ __launch_bounds__(256, 1) void k_corr(const float* __restrict__ X) {
    extern __shared__ u32 cs[];
    u32* xpE = cs; u32* xpO = cs + 4360; u32* xb = cs + 8720;
    const int tid = threadIdx.x, wid = tid >> 5, lane = tid & 31;
    const int dh = blockIdx.x, cp = blockIdx.y, b = blockIdx.z;
    const float* Xb = X + (size_t)b * 65536;
    const float* Xc = Xb + cp * 8192;

    for (int i = tid; i < 4360; i += 256) {     // arr[j] = Xp[c', j-255], pairs
        int t = 2 * i - 255;
        float x0 = (t >= 0 && t < 8192) ? Xc[t] : 0.0f;
        float x1 = (t + 1 >= 0 && t + 1 < 8192) ? Xc[t + 1] : 0.0f;
        float x2 = (t + 2 >= 0 && t + 2 < 8192) ? Xc[t + 2] : 0.0f;
        xpE[i] = (bfb(x1) << 16) | bfb(x0);
        xpO[i] = (bfb(x2) << 16) | bfb(x1);
    }

    float acc[2][4];
    #pragma unroll
    for (int mt = 0; mt < 2; mt++) { acc[mt][0] = acc[mt][1] = acc[mt][2] = acc[mt][3] = 0.0f; }

    const int r0 = lane >> 2, kp = (lane & 3) * 2;
    const int d0 = dh * 256 + wid * 32;
    const u32* arr = (r0 & 1) ? xpO : xpE;
    const int Ioff = (d0 + r0 + kp) >> 1;
    const int nb = (lane >> 2) * 512 + (lane & 3);

    for (int mc = 0; mc < 8; mc++) {
        __syncthreads();
        for (int i2 = tid; i2 < 4096; i2 += 256) {
            int ch = i2 >> 9, ii = i2 & 511;
            float2 v = *(const float2*)(Xb + ch * 8192 + mc * 1024 + 2 * ii);
            xb[i2] = (bfb(v.y) << 16) | bfb(v.x);
        }
        __syncthreads();
        const int Ib = mc * 512 + Ioff;
        #pragma unroll 8
        for (int kc = 0; kc < 64; kc++) {
            int I = Ib + kc * 8;
            u32 qa[5];
            #pragma unroll
            for (int j = 0; j < 5; j++) qa[j] = arr[I + 4 * j];
            u32 b0 = xb[nb + kc * 8], b1 = xb[nb + kc * 8 + 4];
            #pragma unroll
            for (int mt = 0; mt < 2; mt++)
                mma16816(acc[mt][0], acc[mt][1], acc[mt][2], acc[mt][3],
                         qa[2 * mt], qa[2 * mt + 1], qa[2 * mt + 1], qa[2 * mt + 2], b0, b1);
        }
    }
    const int c0 = (lane & 3) * 2;
    #pragma unroll
    for (int mt = 0; mt < 2; mt++) {
        int di = d0 + mt * 16 + r0;
        atomicAdd(&g_r[(cp * 512 + di) * 8 + c0],     acc[mt][0]);
        atomicAdd(&g_r[(cp * 512 + di) * 8 + c0 + 1], acc[mt][1]);
        atomicAdd(&g_r[(cp * 512 + di + 8) * 8 + c0],     acc[mt][2]);
        atomicAdd(&g_r[(cp * 512 + di + 8) * 8 + c0 + 1], acc[mt][3]);
    }
}

// Fused edge products + prefix scan, register-windowed, partial accumulators.
#define HT_SMEM ((16 * 640 + 128 * 16) * 4)
__global__ __launch_bounds__(256) void k_ht2(const float* __restrict__ X) {
    extern __shared__ float hs[];
    float* xp = hs;                 // [b][640]
    float* xc = hs + 16 * 640;      // [m][16]  (m = 0..127, row 127 zero)
    const int cc = blockIdx.x, c = cc >> 3, cq = cc & 7;
    const int tail = blockIdx.y;
    const int t = threadIdx.x;      // di = 2t, 2t+1
    float* O = (tail ? g_T : g_H) + (size_t)(cc * 128) * 512;

    for (int i = t; i < 16 * 640; i += 256) {
        int b = i / 640, j = i - b * 640;
        const float* Xq = X + (size_t)b * 65536 + cq * 8192;
        float v;
        if (!tail) v = (j >= 255 && j < 637) ? Xq[j - 255] : 0.0f;
        else       v = (j <= 381) ? Xq[7810 + j] : 0.0f;
        xp[i] = v;
    }
    for (int i = t; i < 128 * 16; i += 256) {
        int m = i >> 4, b = i & 15;
        const float* Xc2 = X + (size_t)b * 65536 + c * 8192;
        xc[i] = (m < 127) ? (tail ? Xc2[8191 - m] : Xc2[m]) : 0.0f;
    }
    __syncthreads();

    const float2* xp2 = (const float2*)xp;   // [b][320] pairs
    float2 Pc[16], Pn[16];
    #pragma unroll
    for (int b = 0; b < 16; b++)
        Pc[b] = xp2[b * 320 + (tail ? (63 + t) : t)];

    float p0[4], p1[4];                       // persistent partials (4 b each)
    #pragma unroll
    for (int g = 0; g < 4; g++) { p0[g] = 0.0f; p1[g] = 0.0f; }
    *(float2*)&O[2 * t] = make_float2(0.0f, 0.0f);   // m = 0 row

    for (int s = 0; s < 64; s++) {
        int pi = tail ? (62 - s + t) : (t + s + 1);
        if (pi < 0) pi = 0;                          // tail s=63,t=0 guard (unused value)
        #pragma unroll
        for (int b = 0; b < 16; b++)
            Pn[b] = xp2[b * 320 + pi];

        {
            const float4* xr = (const float4*)&xc[(2 * s) * 16];
            float4 x0 = xr[0], x1 = xr[1], x2 = xr[2], x3 = xr[3];
            float xv[16] = {x0.x, x0.y, x0.z, x0.w, x1.x, x1.y, x1.z, x1.w,
                            x2.x, x2.y, x2.z, x2.w, x3.x, x3.y, x3.z, x3.w};
            #pragma unroll
            for (int g = 0; g < 4; g++)
                #pragma unroll
                for (int q = 0; q < 4; q++) {
                    int b = g * 4 + q;
                    p0[g] += xv[b] * Pc[b].x;
                    p1[g] += xv[b] * Pc[b].y;
                }
            *(float2*)&O[(size_t)(2 * s + 1) * 512 + 2 * t] =
                make_float2((p0[0] + p0[1]) + (p0[2] + p0[3]),
                            (p1[0] + p1[1]) + (p1[2] + p1[3]));
        }
        if (s < 63) {
            const float4* xr = (const float4*)&xc[(2 * s + 1) * 16];
            float4 x0 = xr[0], x1 = xr[1], x2 = xr[2], x3 = xr[3];
            float xv[16] = {x0.x, x0.y, x0.z, x0.w, x1.x, x1.y, x1.z, x1.w,
                            x2.x, x2.y, x2.z, x2.w, x3.x, x3.y, x3.z, x3.w};
            if (!tail) {
                #pragma unroll
                for (int g = 0; g < 4; g++)
                    #pragma unroll
                    for (int q = 0; q < 4; q++) {
                        int b = g * 4 + q;
                        p0[g] += xv[b] * Pc[b].y;
                        p1[g] += xv[b] * Pn[b].x;
                    }
            } else {
                #pragma unroll
                for (int g = 0; g < 4; g++)
                    #pragma unroll
                    for (int q = 0; q < 4; q++) {
                        int b = g * 4 + q;
                        p0[g] += xv[b] * Pn[b].y;
                        p1[g] += xv[b] * Pc[b].x;
                    }
            }
            *(float2*)&O[(size_t)(2 * s + 2) * 512 + 2 * t] =
                make_float2((p0[0] + p0[1]) + (p0[2] + p0[3]),
                            (p1[0] + p1[1]) + (p1[2] + p1[3]));
        }
        #pragma unroll
        for (int b = 0; b < 16; b++) Pc[b] = Pn[b];
    }
}

// M = Wt * Wt^T over F: upper-triangle tiles only (M symmetric).
// 1D grid of 136 blocks -> (bx, by) with bx >= by via triangular decode.
#define GEMM_SMEM (65536 + 1024)
__global__ __launch_bounds__(256, 2) void k_gemm() {
    extern __shared__ char sm[];
    u32 raw = smem_u32(sm);
    u32 sb = (raw + 1023u) & ~1023u;
    const int tid = threadIdx.x, wid = tid >> 5, lane = tid & 31;
    const int warp_m = wid & 1, warp_n = wid >> 1;
    int by = 0, bres = blockIdx.x;
    while (bres >= 16 - by) { bres -= 16 - by; by++; }
    const int bx = by + bres;                 // bx >= by
    const u64 wt = to_global(g_Wt4);

    {   // prologue chunk 0
        u64 sa = wt + (u64)(by * 16) * 16384u;
        u64 sg = wt + (u64)(bx * 16) * 16384u;
        for (int i = 0; i < 4; i++) { int e = tid + i * 256; cpa16(sb + e * 16u, sa + (u64)e * 16u); }
        for (int i = 0; i < 4; i++) { int e = tid + i * 256; cpa16(sb + 16384u + e * 16u, sg + (u64)e * 16u); }
        CP_COMMIT();
    }

    float acc[4][4][4];
    #pragma unroll
    for (int mt = 0; mt < 4; mt++)
        #pragma unroll
        for (int nt = 0; nt < 4; nt++)
            #pragma unroll
            for (int r = 0; r < 4; r++) acc[mt][nt][r] = 0.0f;

    const u32 sw = (u32)((lane & 7) << 4);
    const u32 lanecol = (u32)((lane >> 4) * 16);
    u32 am[4], bn[4], bsw[4];
    #pragma unroll
    for (int mt = 0; mt < 4; mt++)
        am[mt] = (u32)(warp_m * 64 + (lane & 15) + mt * 16) * 128u + (lanecol ^ sw);
    #pragma unroll
    for (int nt = 0; nt < 4; nt++) {
        u32 n = (u32)(warp_n * 32 + nt * 8 + (lane >> 2));
        bn[nt] = n * 128u + (u32)((lane & 3) * 4);
        bsw[nt] = (n & 7) << 4;
    }

    for (int ci = 0; ci < 16; ci++) {
        CP_WAIT0();
        __syncthreads();
        if (ci < 15) {
            u32 p = (u32)((ci + 1) & 1) * 32768u;
            u64 sa = wt + (u64)(by * 16 + ci + 1) * 16384u;
            u64 sg = wt + (u64)(bx * 16 + ci + 1) * 16384u;
            for (int i = 0; i < 4; i++) { int e = tid + i * 256; cpa16(sb + p + e * 16u, sa + (u64)e * 16u); }
            for (int i = 0; i < 4; i++) { int e = tid + i * 256; cpa16(sb + p + 16384u + e * 16u, sg + (u64)e * 16u); }
            CP_COMMIT();
        }
        const u32 at = sb + (u32)(ci & 1) * 32768u;
        const u32 bt = at + 16384u;
        #pragma unroll
        for (int ks = 0; ks < 4; ks++) {
            u32 bf0[4], bf1[4];
            #pragma unroll
            for (int nt = 0; nt < 4; nt++) {
                u32 x = bn[nt] + (u32)(ks * 32);
                bf0[nt] = lds32(bt + (x ^ bsw[nt]));
                bf1[nt] = lds32(bt + ((x + 16u) ^ bsw[nt]));
            }
            #pragma unroll
            for (int mt = 0; mt < 4; mt++) {
                u32 a0, a1, a2, a3;
                ldmatrix_x4(a0, a1, a2, a3, (at + am[mt]) ^ (u32)(ks << 5));
                #pragma unroll
                for (int nt = 0; nt < 4; nt++)
                    mma16816(acc[mt][nt][0], acc[mt][nt][1], acc[mt][nt][2], acc[mt][nt][3],
                             a0, a1, a2, a3, bf0[nt], bf1[nt]);
            }
        }
    }
    #pragma unroll
    for (int mt = 0; mt < 4; mt++) {
        int kR = by * 128 + warp_m * 64 + mt * 16 + (lane >> 2);
        #pragma unroll
        for (int nt = 0; nt < 4; nt++) {
            int col = bx * 128 + warp_n * 32 + nt * 8 + (lane & 3) * 2;
            *(float2*)&g_M[(size_t)kR * 2048 + col] = make_float2(acc[mt][nt][0], acc[mt][nt][1]);
            *(float2*)&g_M[(size_t)(kR + 8) * 2048 + col] = make_float2(acc[mt][nt][2], acc[mt][nt][3]);
        }
    }
}

// Q via symmetry: block i handles rows k = i and k' = 2039-i, each summing
// j >= k with weight 2 for j > k (M and G symmetric). 1020 balanced blocks.
__global__ __launch_bounds__(256, 4) void k_qdot() {
    __shared__ unsigned char lc[2040];
    __shared__ unsigned short lt[2040];
    __shared__ float ws[8];
    const int tid = threadIdx.x;
    for (int i = tid; i < 2040; i += 256) { int q = i / 255; lc[i] = (unsigned char)q; lt[i] = (unsigned short)(i - q * 255); }
    __syncthreads();
    float a = 0.0f;
    #pragma unroll
    for (int half = 0; half < 2; half++) {
        const int k = half ? (2039 - (int)blockIdx.x) : (int)blockIdx.x;
        const int kc = lc[k], kt = lt[k];
        const int mh = kt > 127 ? kt - 127 : 0;
        const int ml = kt < 127 ? 127 - kt : 0;
        const float* Mrow = g_M + (size_t)k * 2048;
        const size_t Hb = (size_t)(kc * 1024 + mh) * 512;
        const size_t Tb = (size_t)(kc * 1024 + ml) * 512;
        for (int j = k + tid; j < 2040; j += 256) {
            int cp = lc[j];
            int di = (int)lt[j] - kt + 255;
            float G = g_r[((cp << 9) + di) * 8 + kc]
                    - g_H[Hb + (size_t)cp * 65536 + di]
                    - g_T[Tb + (size_t)cp * 65536 + di];
            float w = (j == k) ? 1.0f : 2.0f;
            a += w * Mrow[j] * G;
        }
    }
    #pragma unroll
    for (int o = 16; o; o >>= 1) a += __shfl_xor_sync(0xffffffffu, a, o);
    if ((tid & 31) == 0) ws[tid >> 5] = a;
    __syncthreads();
    if (tid == 0) {
        float s = 0.0f;
        for (int w = 0; w < 8; w++) s += ws[w];
        atomicAdd(&g_acc, (double)s);
    }
}

__global__ __launch_bounds__(256, 4) void k_cross(const float* __restrict__ F) {
    __shared__ float ws[8];
    const int f = blockIdx.x, cf = f & 7;
    const float* Wf = F + (size_t)f * 2040;
    float a = 0.0f;
    for (int k = threadIdx.x; k < 2040; k += 256) {
        int cp = k / 255, tau = k - cp * 255;
        a += Wf[k] * g_r[((cp << 9) + tau + 128) * 8 + cf];
    }
    #pragma unroll
    for (int o = 16; o; o >>= 1) a += __shfl_xor_sync(0xffffffffu, a, o);
    if ((threadIdx.x & 31) == 0) ws[threadIdx.x >> 5] = a;
    __syncthreads();
    if (threadIdx.x == 0) {
        float s = 0.0f;
        for (int w = 0; w < 8; w++) s += ws[w];
        atomicAdd(&g_acc, -2.0 * (double)s);
    }
}

__global__ void k_final(float* out) {
    double s = g_acc;
    for (int c = 0; c < 8; c++) s += 128.0 * (double)g_r[((c << 9) + 255) * 8 + c];
    out[0] = (float)(s * (1.0 / 8388608.0));
    g_acc = 0.0;
}

extern "C" void kernel_launch(void* const* d_in, const int* in_sizes, int n_in,
                              void* d_out, int out_size) {
    const float* X = (const float*)d_in[0];
    const float* F = (const float*)d_in[1];
    if (n_in >= 2 && in_sizes[0] == 16 * 64 * 8 * 255) {
        const float* t = X; X = F; F = t;
    }
    static int configured = 0;
    if (!configured) {
        cudaFuncSetAttribute(k_corr, cudaFuncAttributeMaxDynamicSharedMemorySize, CORR_SMEM);
        cudaFuncSetAttribute(k_ht2, cudaFuncAttributeMaxDynamicSharedMemorySize, HT_SMEM);
        cudaFuncSetAttribute(k_gemm, cudaFuncAttributeMaxDynamicSharedMemorySize, GEMM_SMEM);
        configured = 1;
    }
    k_prep<<<2048, 256>>>(F);                      // also zeroes g_r
    k_corr<<<dim3(2, 8, 16), 256, CORR_SMEM>>>(X);
    k_ht2<<<dim3(64, 2), 256, HT_SMEM>>>(X);
    k_gemm<<<136, 256, GEMM_SMEM>>>();             // upper-triangle tiles only
    k_qdot<<<1020, 256>>>();                       // j >= k, weight-2 off-diag
    k_cross<<<1024, 256>>>(F);
    k_final<<<1, 1>>>((float*)d_out);
}